// round 4
// baseline (speedup 1.0000x reference)
#include <cuda_runtime.h>
#include <math.h>

#define NN   50000
#define EE   200000
#define BB   2048
#define ATT  16
#define ETT  4
#define H    32
#define LL   3
#define LAT  64
#define HLD  256
#define FEAT 245
#define FEATP 248
#define MAXN 50.0f
#define GPB  8
#define NBU  592   // grid-stride blocks for k_update

// ---------------- scratch (device globals; no allocation allowed) ----------------
__device__ float g_h[NN * H];            // current (normalized) node features
__device__ float g_hnew[NN * H];         // pre-BN features (relu(nx)+h)
__device__ float g_P[NN * 5 * H];        // per-node h@W_t (t=0..3) and h@Bmat (t=4)
__device__ float g_hr[NN * H];           // per-node h@root_w
__device__ float g_agg[NN * H];
__device__ float g_deg[NN];
__device__ float g_invdeg[NN];
__device__ float g_cnt[BB];
__device__ float g_feats[BB * FEAT];
__device__ float g_poolsum[LL * BB * H];
__device__ float g_poolmax[LL * BB * H];
__device__ float g_bnpartS[NBU * H];
__device__ float g_bnpartQ[NBU * H];
__device__ float g_bnA[LL * H];
__device__ float g_bnB[LL * H];

// float atomic max via monotone int/uint mapping
__device__ __forceinline__ void atomicMaxFloat(float* addr, float v) {
    if (v >= 0.f) atomicMax((int*)addr, __float_as_int(v));
    else          atomicMin((unsigned int*)addr, __float_as_uint(v));
}

// ---------------- one-time zero (float4) ----------------
__global__ void k_zero() {
    int i = blockIdx.x * blockDim.x + threadIdx.x;
    const float4 z4 = make_float4(0.f, 0.f, 0.f, 0.f);
    const float4 ninf4 = make_float4(-INFINITY, -INFINITY, -INFINITY, -INFINITY);
    if (i < NN * H / 4)      ((float4*)g_agg)[i] = z4;
    if (i < BB * FEAT / 4)   ((float4*)g_feats)[i] = z4;
    if (i < NN / 4)          ((float4*)g_deg)[i] = z4;
    if (i < BB / 4)          ((float4*)g_cnt)[i] = z4;
    if (i < LL * BB * H / 4) { ((float4*)g_poolsum)[i] = z4; ((float4*)g_poolmax)[i] = ninf4; }
}

// ---------------- fused edge stats + x pools ----------------
__global__ void k_stats(const int* __restrict__ ei, const float* __restrict__ et,
                        const float* __restrict__ x, const int* __restrict__ batch) {
    int i = blockIdx.x * blockDim.x + threadIdx.x;
    if (i < NN * ATT) {
        int n = i / ATT, c = i % ATT;
        int g = batch[n];
        float v = x[i];
        atomicAdd(&g_feats[g * FEAT + 21 + c], v);
        atomicMaxFloat(&g_feats[g * FEAT + 37 + c], v);   // x >= 0, zero-init safe
        if (c == 0) atomicAdd(&g_cnt[g], 1.f);
    }
    if (i < EE) {
        int s = ei[i];
        int t = ei[EE + i];
        atomicAdd(&g_deg[t], 1.f);
        int g = batch[s];
        const float inv = 1.f / MAXN;
#pragma unroll
        for (int j = 0; j < ETT; j++)
            atomicAdd(&g_feats[g * FEAT + 1 + j], et[i * ETT + j] * inv);
    }
}

// ---------------- initial node MLP (thread per node; broadcast-LDS weights, no shfl)
//                  + fused invdeg / x-feature finish ----------------
__global__ void k_init_mlp(const float* __restrict__ x,
                           const float* __restrict__ w0, const float* __restrict__ b0,
                           const float* __restrict__ w1, const float* __restrict__ b1) {
    __shared__ float sw0[ATT * H], sw1[H * H], sb0[H], sb1[H];
    int tid = threadIdx.x;
    for (int i = tid; i < ATT * H; i += blockDim.x) sw0[i] = w0[i];
    for (int i = tid; i < H * H;  i += blockDim.x) sw1[i] = w1[i];
    if (tid < H) { sb0[tid] = b0[tid]; sb1[tid] = b1[tid]; }
    __syncthreads();

    int gid = blockIdx.x * blockDim.x + tid;
    // fused: invdeg + x-feature finish (depend only on k_stats)
    if (gid < NN) g_invdeg[gid] = 1.f / fmaxf(g_deg[gid], 1.f);
    if (gid < BB * ATT) {
        int g = gid / ATT, c = gid % ATT;
        float cnt = g_cnt[g];
        float sum = g_feats[g * FEAT + 21 + c];
        g_feats[g * FEAT + 5 + c]  = sum / MAXN;
        g_feats[g * FEAT + 21 + c] = sum / fmaxf(cnt, 1.f);
        if (cnt <= 0.f) g_feats[g * FEAT + 37 + c] = 0.f;
        if (c == 0) g_feats[g * FEAT] = cnt / MAXN;
    }

    int n = gid;
    if (n >= NN) return;
    float xr[ATT];
#pragma unroll
    for (int q = 0; q < ATT / 4; q++) {
        float4 v = *(const float4*)&x[n * ATT + q * 4];
        xr[q * 4 + 0] = v.x; xr[q * 4 + 1] = v.y; xr[q * 4 + 2] = v.z; xr[q * 4 + 3] = v.w;
    }
    float t[H];
#pragma unroll
    for (int o = 0; o < H / 4; o++) {
        float4 bv = *(const float4*)&sb0[o * 4];
        t[o * 4 + 0] = bv.x; t[o * 4 + 1] = bv.y; t[o * 4 + 2] = bv.z; t[o * 4 + 3] = bv.w;
    }
#pragma unroll
    for (int a = 0; a < ATT; a++) {
        float xa = xr[a];
#pragma unroll
        for (int o = 0; o < H / 4; o++) {
            float4 w = *(const float4*)&sw0[a * H + o * 4];   // broadcast LDS.128
            t[o * 4 + 0] = fmaf(xa, w.x, t[o * 4 + 0]);
            t[o * 4 + 1] = fmaf(xa, w.y, t[o * 4 + 1]);
            t[o * 4 + 2] = fmaf(xa, w.z, t[o * 4 + 2]);
            t[o * 4 + 3] = fmaf(xa, w.w, t[o * 4 + 3]);
        }
    }
    float hv[H];
#pragma unroll
    for (int o = 0; o < H / 4; o++) {
        float4 bv = *(const float4*)&sb1[o * 4];
        hv[o * 4 + 0] = bv.x; hv[o * 4 + 1] = bv.y; hv[o * 4 + 2] = bv.z; hv[o * 4 + 3] = bv.w;
    }
#pragma unroll
    for (int k = 0; k < H; k++) {
        float tk = fmaxf(t[k], 0.f);
#pragma unroll
        for (int o = 0; o < H / 4; o++) {
            float4 w = *(const float4*)&sw1[k * H + o * 4];   // broadcast LDS.128
            hv[o * 4 + 0] = fmaf(tk, w.x, hv[o * 4 + 0]);
            hv[o * 4 + 1] = fmaf(tk, w.y, hv[o * 4 + 1]);
            hv[o * 4 + 2] = fmaf(tk, w.z, hv[o * 4 + 2]);
            hv[o * 4 + 3] = fmaf(tk, w.w, hv[o * 4 + 3]);
        }
    }
#pragma unroll
    for (int o = 0; o < H / 4; o++)
        *(float4*)&g_h[n * H + o * 4] = make_float4(hv[o*4], hv[o*4+1], hv[o*4+2], hv[o*4+3]);
}

// ---------------- precompute GEMM: P[n,t,:], hr[n,:]; applies prev-layer BN affine
//                  8 nodes per warp ----------------
__global__ void k_precompute(const float* __restrict__ enw, const float* __restrict__ enb,
                             const float* __restrict__ rw, int l) {
    __shared__ float sW[6 * H * H];   // 24 KB: 4 edge-type mats + bias mat + root mat
    int tid = threadIdx.x;
    for (int i = tid; i < 5 * H * H; i += blockDim.x) {
        int t = i >> 10, rest = i & 1023;
        sW[i] = (t < 4) ? enw[(l * ETT + t) * H * H + rest] : enb[l * H * H + rest];
    }
    for (int i = tid; i < H * H; i += blockDim.x)
        sW[5 * H * H + i] = rw[l * H * H + i];
    __syncthreads();

    int warp = (blockIdx.x * blockDim.x + tid) >> 5;
    int lane = tid & 31;
    int nb = warp * 8;
    if (nb >= NN) return;

    float bnA = 0.f, bnB = 0.f;
    if (l > 0) { bnA = g_bnA[(l - 1) * H + lane]; bnB = g_bnB[(l - 1) * H + lane]; }

    float hv[8];
#pragma unroll
    for (int j = 0; j < 8; j++) {
        int n = nb + j;
        if (n < NN) {
            float v;
            if (l == 0) v = g_h[n * H + lane];
            else { v = fmaf(g_hnew[n * H + lane], bnA, bnB); g_h[n * H + lane] = v; }
            hv[j] = v;
        } else hv[j] = 0.f;
    }

    float a0[8], a1[8], a2[8], a3[8], a4[8], a5[8];
#pragma unroll
    for (int j = 0; j < 8; j++) { a0[j]=0.f; a1[j]=0.f; a2[j]=0.f; a3[j]=0.f; a4[j]=0.f; a5[j]=0.f; }
#pragma unroll
    for (int hh = 0; hh < H; hh++) {
        float w0 = sW[0 * 1024 + hh * H + lane];
        float w1 = sW[1 * 1024 + hh * H + lane];
        float w2 = sW[2 * 1024 + hh * H + lane];
        float w3 = sW[3 * 1024 + hh * H + lane];
        float w4 = sW[4 * 1024 + hh * H + lane];
        float w5 = sW[5 * 1024 + hh * H + lane];
#pragma unroll
        for (int j = 0; j < 8; j++) {
            float hb = __shfl_sync(0xffffffffu, hv[j], hh);
            a0[j] = fmaf(hb, w0, a0[j]);
            a1[j] = fmaf(hb, w1, a1[j]);
            a2[j] = fmaf(hb, w2, a2[j]);
            a3[j] = fmaf(hb, w3, a3[j]);
            a4[j] = fmaf(hb, w4, a4[j]);
            a5[j] = fmaf(hb, w5, a5[j]);
        }
    }
#pragma unroll
    for (int j = 0; j < 8; j++) {
        int n = nb + j;
        if (n >= NN) break;
        float* Pr = &g_P[n * 5 * H];
        Pr[0 * H + lane] = a0[j];
        Pr[1 * H + lane] = a1[j];
        Pr[2 * H + lane] = a2[j];
        Pr[3 * H + lane] = a3[j];
        Pr[4 * H + lane] = a4[j];
        g_hr[n * H + lane] = a5[j];
    }
}

// ---------------- edge pass: msg = Σ_t et·P[src,t,:] + P[src,4,:] → scatter-add ----------------
__global__ void k_edge(const int* __restrict__ ei, const float* __restrict__ et) {
    int gid = blockIdx.x * blockDim.x + threadIdx.x;
    int e = gid >> 5;
    int lane = gid & 31;
    if (e >= EE) return;
    int s = ei[e];
    int t = ei[EE + e];
    float etv = (lane < ETT) ? et[e * ETT + lane] : 0.f;
    const float* __restrict__ Pr = &g_P[s * 5 * H];
    float acc = Pr[4 * H + lane];
#pragma unroll
    for (int j = 0; j < ETT; j++)
        acc += __shfl_sync(0xffffffffu, etv, j) * Pr[j * H + lane];
    atomicAdd(&g_agg[t * H + lane], acc);   // lanes hit one 128B line: coalesced RED
}

// ---------------- node update (grid-stride, float4): nx = hr + agg*invdeg + b;
//                  pools; hnew = relu(nx)+h; BN partials; re-zero agg ----------------
__global__ void k_update(const float* __restrict__ cb, const int* __restrict__ batch, int l) {
    __shared__ float ssum[H], ssq[H];
    int tid = threadIdx.x;
    if (tid < H) { ssum[tid] = 0.f; ssq[tid] = 0.f; }
    __syncthreads();
    int c0 = (tid & 7) * 4;    // channel base: stride (NBU*256) is a multiple of 8 quads
    float4 bias = *(const float4*)&cb[l * H + c0];
    float ls0=0.f, ls1=0.f, ls2=0.f, ls3=0.f, lq0=0.f, lq1=0.f, lq2=0.f, lq3=0.f;
    float* psum = &g_poolsum[l * BB * H];
    float* pmax = &g_poolmax[l * BB * H];
    for (int i = blockIdx.x * blockDim.x + tid; i < NN * H / 4; i += gridDim.x * blockDim.x) {
        int n = i >> 3;
        float4 h4 = ((const float4*)g_h)[i];
        float4 a4 = ((const float4*)g_agg)[i];
        float4 r4 = ((const float4*)g_hr)[i];
        float id = g_invdeg[n];
        int g = batch[n];
        float nx0 = bias.x + a4.x * id + r4.x;
        float nx1 = bias.y + a4.y * id + r4.y;
        float nx2 = bias.z + a4.z * id + r4.z;
        float nx3 = bias.w + a4.w * id + r4.w;
        ((float4*)g_agg)[i] = make_float4(0.f, 0.f, 0.f, 0.f);
        float* ps = &psum[g * H + c0];
        float* pm = &pmax[g * H + c0];
        atomicAdd(&ps[0], nx0); atomicMaxFloat(&pm[0], nx0);
        atomicAdd(&ps[1], nx1); atomicMaxFloat(&pm[1], nx1);
        atomicAdd(&ps[2], nx2); atomicMaxFloat(&pm[2], nx2);
        atomicAdd(&ps[3], nx3); atomicMaxFloat(&pm[3], nx3);
        float hp0 = fmaxf(nx0, 0.f) + h4.x;
        float hp1 = fmaxf(nx1, 0.f) + h4.y;
        float hp2 = fmaxf(nx2, 0.f) + h4.z;
        float hp3 = fmaxf(nx3, 0.f) + h4.w;
        ((float4*)g_hnew)[i] = make_float4(hp0, hp1, hp2, hp3);
        ls0 += hp0; lq0 += hp0 * hp0;
        ls1 += hp1; lq1 += hp1 * hp1;
        ls2 += hp2; lq2 += hp2 * hp2;
        ls3 += hp3; lq3 += hp3 * hp3;
    }
    atomicAdd(&ssum[c0 + 0], ls0); atomicAdd(&ssq[c0 + 0], lq0);
    atomicAdd(&ssum[c0 + 1], ls1); atomicAdd(&ssq[c0 + 1], lq1);
    atomicAdd(&ssum[c0 + 2], ls2); atomicAdd(&ssq[c0 + 2], lq2);
    atomicAdd(&ssum[c0 + 3], ls3); atomicAdd(&ssq[c0 + 3], lq3);
    __syncthreads();
    if (tid < H) {
        g_bnpartS[blockIdx.x * H + tid] = ssum[tid];
        g_bnpartQ[blockIdx.x * H + tid] = ssq[tid];
    }
}

// ---------------- fused pool-finish + BN-finish ----------------
__global__ void k_post(const float* __restrict__ gamma, const float* __restrict__ beta, int l) {
    int i = blockIdx.x * blockDim.x + threadIdx.x;
    if (i < BB * H) {
        int g = i / H, k = i % H;
        float cnt = g_cnt[g];
        float m  = g_poolsum[l * BB * H + i] / fmaxf(cnt, 1.f);
        float mx = (cnt > 0.f) ? g_poolmax[l * BB * H + i] : 0.f;
        g_feats[g * FEAT + 53 + l * 2 * H + k]     = m;
        g_feats[g * FEAT + 53 + l * 2 * H + H + k] = mx;
    }
    if (i < H) {
        float s = 0.f, q = 0.f;
        for (int b = 0; b < NBU; b++) {
            s += g_bnpartS[b * H + i];
            q += g_bnpartQ[b * H + i];
        }
        float mu  = s / (float)NN;
        float var = q / (float)NN - mu * mu;
        float A = gamma[l * H + i] * rsqrtf(var + 1e-5f);
        g_bnA[l * H + i] = A;
        g_bnB[l * H + i] = beta[l * H + i] - mu * A;
    }
}

// ---------------- final MLP: feats[B,245]@W0 relu @W1 (8 graphs per block, float4 LDS) ----------------
__global__ void k_final(const float* __restrict__ w0, const float* __restrict__ b0,
                        const float* __restrict__ w1, const float* __restrict__ b1,
                        float* __restrict__ out) {
    __shared__ float sf[GPB * FEATP];
    __shared__ float st[GPB * HLD];
    int tid = threadIdx.x;
    int g0 = blockIdx.x * GPB;
    for (int i = tid; i < GPB * FEATP; i += blockDim.x) {
        int gg = i / FEATP, r = i - gg * FEATP;
        sf[i] = (r < FEAT) ? g_feats[(g0 + gg) * FEAT + r] : 0.f;
    }
    __syncthreads();
    {
        float acc[GPB];
        float bb = b0[tid];
#pragma unroll
        for (int gg = 0; gg < GPB; gg++) acc[gg] = bb;
        for (int i = 0; i < 244; i += 4) {
            float wa = w0[(i + 0) * HLD + tid];
            float wb = w0[(i + 1) * HLD + tid];
            float wc = w0[(i + 2) * HLD + tid];
            float wd = w0[(i + 3) * HLD + tid];
#pragma unroll
            for (int gg = 0; gg < GPB; gg++) {
                float4 f = *(const float4*)&sf[gg * FEATP + i];   // broadcast LDS.128
                acc[gg] = fmaf(f.x, wa, acc[gg]);
                acc[gg] = fmaf(f.y, wb, acc[gg]);
                acc[gg] = fmaf(f.z, wc, acc[gg]);
                acc[gg] = fmaf(f.w, wd, acc[gg]);
            }
        }
        float wl = w0[244 * HLD + tid];
#pragma unroll
        for (int gg = 0; gg < GPB; gg++) acc[gg] = fmaf(sf[gg * FEATP + 244], wl, acc[gg]);
#pragma unroll
        for (int gg = 0; gg < GPB; gg++) st[gg * HLD + tid] = fmaxf(acc[gg], 0.f);
    }
    __syncthreads();
    {
        int col = tid & 127;
        int gbase = (tid >> 7) * 4;
        float bb = b1[col];
        float acc[4];
#pragma unroll
        for (int q = 0; q < 4; q++) acc[q] = bb;
        for (int i = 0; i < HLD; i += 4) {
            float wa = w1[(i + 0) * 2 * LAT + col];
            float wb = w1[(i + 1) * 2 * LAT + col];
            float wc = w1[(i + 2) * 2 * LAT + col];
            float wd = w1[(i + 3) * 2 * LAT + col];
#pragma unroll
            for (int q = 0; q < 4; q++) {
                float4 s4 = *(const float4*)&st[(gbase + q) * HLD + i];  // broadcast LDS.128
                acc[q] = fmaf(s4.x, wa, acc[q]);
                acc[q] = fmaf(s4.y, wb, acc[q]);
                acc[q] = fmaf(s4.z, wc, acc[q]);
                acc[q] = fmaf(s4.w, wd, acc[q]);
            }
        }
#pragma unroll
        for (int q = 0; q < 4; q++) {
            int g = g0 + gbase + q;
            if (col < LAT) out[g * LAT + col] = acc[q];
            else           out[BB * LAT + g * LAT + (col - LAT)] = acc[q];
        }
    }
}

// ---------------- launch ----------------
extern "C" void kernel_launch(void* const* d_in, const int* in_sizes, int n_in,
                              void* d_out, int out_size) {
    const float* x      = (const float*)d_in[0];
    const int*   ei     = (const int*)  d_in[1];
    const float* et     = (const float*)d_in[2];
    const int*   batch  = (const int*)  d_in[3];
    const float* mlp0_w = (const float*)d_in[4];
    const float* mlp0_b = (const float*)d_in[5];
    const float* mlp1_w = (const float*)d_in[6];
    const float* mlp1_b = (const float*)d_in[7];
    const float* enw    = (const float*)d_in[8];
    const float* enb    = (const float*)d_in[9];
    const float* rw     = (const float*)d_in[10];
    const float* cb     = (const float*)d_in[11];
    const float* gamma  = (const float*)d_in[12];
    const float* beta   = (const float*)d_in[13];
    const float* f0w    = (const float*)d_in[14];
    const float* f0b    = (const float*)d_in[15];
    const float* f1w    = (const float*)d_in[16];
    const float* f1b    = (const float*)d_in[17];
    float* out = (float*)d_out;

    k_zero<<<(NN * H / 4 + 255) / 256, 256>>>();
    k_stats<<<(NN * ATT + 255) / 256, 256>>>(ei, et, x, batch);
    k_init_mlp<<<(NN + 255) / 256, 256>>>(x, mlp0_w, mlp0_b, mlp1_w, mlp1_b);

    for (int l = 0; l < LL; l++) {
        k_precompute<<<(NN + 63) / 64, 256>>>(enw, enb, rw, l);   // 8 warps * 8 nodes per block
        k_edge<<<(EE * 32 + 255) / 256, 256>>>(ei, et);
        k_update<<<NBU, 256>>>(cb, batch, l);
        k_post<<<(BB * H + 255) / 256, 256>>>(gamma, beta, l);
    }

    k_final<<<BB / GPB, 256>>>(f0w, f0b, f1w, f1b, out);
}

// round 5
// speedup vs baseline: 1.1329x; 1.1329x over previous
#include <cuda_runtime.h>
#include <math.h>

#define NN   50000
#define EE   200000
#define BB   2048
#define ATT  16
#define ETT  4
#define H    32
#define LL   3
#define LAT  64
#define HLD  256
#define FEAT 245
#define FEATP 248
#define MAXN 50.0f
#define GPB  8
#define NBU  592   // grid-stride blocks for k_update

// ---------------- scratch (device globals; no allocation allowed) ----------------
__device__ float g_h[NN * H];            // current (normalized) node features
__device__ float g_hnew[NN * H];         // pre-BN features (relu(nx)+h)
__device__ float g_P[NN * 5 * H];        // per-node h@W_t (t=0..3) and h@Bmat (t=4)
__device__ float g_hr[NN * H];           // per-node h@root_w
__device__ float g_agg[NN * H];
__device__ float g_deg[NN];
__device__ float g_invdeg[NN];
__device__ float g_cnt[BB];
__device__ float g_feats[BB * FEAT];
__device__ float g_poolsum[LL * BB * H];
__device__ float g_poolmax[LL * BB * H];
__device__ float g_bnpartS[NBU * H];
__device__ float g_bnpartQ[NBU * H];
__device__ float g_bnA[LL * H];
__device__ float g_bnB[LL * H];

// float atomic max via monotone int/uint mapping
__device__ __forceinline__ void atomicMaxFloat(float* addr, float v) {
    if (v >= 0.f) atomicMax((int*)addr, __float_as_int(v));
    else          atomicMin((unsigned int*)addr, __float_as_uint(v));
}

// ---------------- one-time zero (float4) ----------------
__global__ void k_zero() {
    int i = blockIdx.x * blockDim.x + threadIdx.x;
    const float4 z4 = make_float4(0.f, 0.f, 0.f, 0.f);
    const float4 ninf4 = make_float4(-INFINITY, -INFINITY, -INFINITY, -INFINITY);
    if (i < NN * H / 4)      ((float4*)g_agg)[i] = z4;
    if (i < BB * FEAT / 4)   ((float4*)g_feats)[i] = z4;
    if (i < NN / 4)          ((float4*)g_deg)[i] = z4;
    if (i < BB / 4)          ((float4*)g_cnt)[i] = z4;
    if (i < LL * BB * H / 4) { ((float4*)g_poolsum)[i] = z4; ((float4*)g_poolmax)[i] = ninf4; }
}

// ---------------- fused edge stats + x pools ----------------
__global__ void k_stats(const int* __restrict__ ei, const float* __restrict__ et,
                        const float* __restrict__ x, const int* __restrict__ batch) {
    int i = blockIdx.x * blockDim.x + threadIdx.x;
    if (i < NN * ATT) {
        int n = i / ATT, c = i % ATT;
        int g = batch[n];
        float v = x[i];
        atomicAdd(&g_feats[g * FEAT + 21 + c], v);
        atomicMaxFloat(&g_feats[g * FEAT + 37 + c], v);   // x >= 0, zero-init safe
        if (c == 0) atomicAdd(&g_cnt[g], 1.f);
    }
    if (i < EE) {
        int s = ei[i];
        int t = ei[EE + i];
        atomicAdd(&g_deg[t], 1.f);
        int g = batch[s];
        const float inv = 1.f / MAXN;
#pragma unroll
        for (int j = 0; j < ETT; j++)
            atomicAdd(&g_feats[g * FEAT + 1 + j], et[i * ETT + j] * inv);
    }
}

// ---------------- initial node MLP (thread per node; broadcast-LDS.128 weights)
//                  + fused invdeg / x-feature finish ----------------
__global__ void k_init_mlp(const float* __restrict__ x,
                           const float* __restrict__ w0, const float* __restrict__ b0,
                           const float* __restrict__ w1, const float* __restrict__ b1) {
    __shared__ float sw0[ATT * H], sw1[H * H], sb0[H], sb1[H];
    int tid = threadIdx.x;
    for (int i = tid; i < ATT * H; i += blockDim.x) sw0[i] = w0[i];
    for (int i = tid; i < H * H;  i += blockDim.x) sw1[i] = w1[i];
    if (tid < H) { sb0[tid] = b0[tid]; sb1[tid] = b1[tid]; }
    __syncthreads();

    int gid = blockIdx.x * blockDim.x + tid;
    // fused: invdeg + x-feature finish (depend only on k_stats)
    if (gid < NN) g_invdeg[gid] = 1.f / fmaxf(g_deg[gid], 1.f);
    if (gid < BB * ATT) {
        int g = gid / ATT, c = gid % ATT;
        float cnt = g_cnt[g];
        float sum = g_feats[g * FEAT + 21 + c];
        g_feats[g * FEAT + 5 + c]  = sum / MAXN;
        g_feats[g * FEAT + 21 + c] = sum / fmaxf(cnt, 1.f);
        if (cnt <= 0.f) g_feats[g * FEAT + 37 + c] = 0.f;
        if (c == 0) g_feats[g * FEAT] = cnt / MAXN;
    }

    int n = gid;
    if (n >= NN) return;
    float xr[ATT];
#pragma unroll
    for (int q = 0; q < ATT / 4; q++) {
        float4 v = *(const float4*)&x[n * ATT + q * 4];
        xr[q * 4 + 0] = v.x; xr[q * 4 + 1] = v.y; xr[q * 4 + 2] = v.z; xr[q * 4 + 3] = v.w;
    }
    float t[H];
#pragma unroll
    for (int o = 0; o < H / 4; o++) {
        float4 bv = *(const float4*)&sb0[o * 4];
        t[o * 4 + 0] = bv.x; t[o * 4 + 1] = bv.y; t[o * 4 + 2] = bv.z; t[o * 4 + 3] = bv.w;
    }
#pragma unroll
    for (int a = 0; a < ATT; a++) {
        float xa = xr[a];
#pragma unroll
        for (int o = 0; o < H / 4; o++) {
            float4 w = *(const float4*)&sw0[a * H + o * 4];   // broadcast LDS.128
            t[o * 4 + 0] = fmaf(xa, w.x, t[o * 4 + 0]);
            t[o * 4 + 1] = fmaf(xa, w.y, t[o * 4 + 1]);
            t[o * 4 + 2] = fmaf(xa, w.z, t[o * 4 + 2]);
            t[o * 4 + 3] = fmaf(xa, w.w, t[o * 4 + 3]);
        }
    }
    float hv[H];
#pragma unroll
    for (int o = 0; o < H / 4; o++) {
        float4 bv = *(const float4*)&sb1[o * 4];
        hv[o * 4 + 0] = bv.x; hv[o * 4 + 1] = bv.y; hv[o * 4 + 2] = bv.z; hv[o * 4 + 3] = bv.w;
    }
#pragma unroll
    for (int k = 0; k < H; k++) {
        float tk = fmaxf(t[k], 0.f);
#pragma unroll
        for (int o = 0; o < H / 4; o++) {
            float4 w = *(const float4*)&sw1[k * H + o * 4];   // broadcast LDS.128
            hv[o * 4 + 0] = fmaf(tk, w.x, hv[o * 4 + 0]);
            hv[o * 4 + 1] = fmaf(tk, w.y, hv[o * 4 + 1]);
            hv[o * 4 + 2] = fmaf(tk, w.z, hv[o * 4 + 2]);
            hv[o * 4 + 3] = fmaf(tk, w.w, hv[o * 4 + 3]);
        }
    }
#pragma unroll
    for (int o = 0; o < H / 4; o++)
        *(float4*)&g_h[n * H + o * 4] = make_float4(hv[o*4], hv[o*4+1], hv[o*4+2], hv[o*4+3]);
}

// ---------------- precompute GEMM: P[n,t,:], hr[n,:]; applies prev-layer BN affine
//                  4 nodes per warp (R3 config: regs ~40, higher occupancy) ----------------
__global__ void k_precompute(const float* __restrict__ enw, const float* __restrict__ enb,
                             const float* __restrict__ rw, int l) {
    __shared__ float sW[6 * H * H];   // 24 KB: 4 edge-type mats + bias mat + root mat
    int tid = threadIdx.x;
    for (int i = tid; i < 5 * H * H; i += blockDim.x) {
        int t = i >> 10, rest = i & 1023;
        sW[i] = (t < 4) ? enw[(l * ETT + t) * H * H + rest] : enb[l * H * H + rest];
    }
    for (int i = tid; i < H * H; i += blockDim.x)
        sW[5 * H * H + i] = rw[l * H * H + i];
    __syncthreads();

    int warp = (blockIdx.x * blockDim.x + tid) >> 5;
    int lane = tid & 31;
    int nb = warp * 4;
    if (nb >= NN) return;

    float bnA = 0.f, bnB = 0.f;
    if (l > 0) { bnA = g_bnA[(l - 1) * H + lane]; bnB = g_bnB[(l - 1) * H + lane]; }

    float hv[4];
#pragma unroll
    for (int j = 0; j < 4; j++) {
        int n = nb + j;
        if (n < NN) {
            float v;
            if (l == 0) v = g_h[n * H + lane];
            else { v = fmaf(g_hnew[n * H + lane], bnA, bnB); g_h[n * H + lane] = v; }
            hv[j] = v;
        } else hv[j] = 0.f;
    }

    float a0[4] = {0,0,0,0}, a1[4] = {0,0,0,0}, a2[4] = {0,0,0,0};
    float a3[4] = {0,0,0,0}, a4[4] = {0,0,0,0}, a5[4] = {0,0,0,0};
#pragma unroll
    for (int hh = 0; hh < H; hh++) {
        float w0 = sW[0 * 1024 + hh * H + lane];
        float w1 = sW[1 * 1024 + hh * H + lane];
        float w2 = sW[2 * 1024 + hh * H + lane];
        float w3 = sW[3 * 1024 + hh * H + lane];
        float w4 = sW[4 * 1024 + hh * H + lane];
        float w5 = sW[5 * 1024 + hh * H + lane];
#pragma unroll
        for (int j = 0; j < 4; j++) {
            float hb = __shfl_sync(0xffffffffu, hv[j], hh);
            a0[j] = fmaf(hb, w0, a0[j]);
            a1[j] = fmaf(hb, w1, a1[j]);
            a2[j] = fmaf(hb, w2, a2[j]);
            a3[j] = fmaf(hb, w3, a3[j]);
            a4[j] = fmaf(hb, w4, a4[j]);
            a5[j] = fmaf(hb, w5, a5[j]);
        }
    }
#pragma unroll
    for (int j = 0; j < 4; j++) {
        int n = nb + j;
        if (n >= NN) break;
        float* Pr = &g_P[n * 5 * H];
        Pr[0 * H + lane] = a0[j];
        Pr[1 * H + lane] = a1[j];
        Pr[2 * H + lane] = a2[j];
        Pr[3 * H + lane] = a3[j];
        Pr[4 * H + lane] = a4[j];
        g_hr[n * H + lane] = a5[j];
    }
}

// ---------------- edge pass: msg = Σ_t et·P[src,t,:] + P[src,4,:] → scatter-add ----------------
__global__ void k_edge(const int* __restrict__ ei, const float* __restrict__ et) {
    int gid = blockIdx.x * blockDim.x + threadIdx.x;
    int e = gid >> 5;
    int lane = gid & 31;
    if (e >= EE) return;
    int s = ei[e];
    int t = ei[EE + e];
    float etv = (lane < ETT) ? et[e * ETT + lane] : 0.f;
    const float* __restrict__ Pr = &g_P[s * 5 * H];
    float acc = Pr[4 * H + lane];
#pragma unroll
    for (int j = 0; j < ETT; j++)
        acc += __shfl_sync(0xffffffffu, etv, j) * Pr[j * H + lane];
    atomicAdd(&g_agg[t * H + lane], acc);   // lanes hit one 128B line: coalesced RED
}

// ---------------- node update (grid-stride streaming, lane=channel): nx = hr + agg*invdeg + b;
//                  pools (warp-coalesced single-line atomics); hnew = relu(nx)+h; BN partials; re-zero agg ----------------
__global__ void k_update(const float* __restrict__ cb, const int* __restrict__ batch, int l) {
    __shared__ float ssum[H], ssq[H];
    int tid = threadIdx.x;
    int lane = tid & 31;
    if (tid < H) { ssum[tid] = 0.f; ssq[tid] = 0.f; }
    __syncthreads();
    float bias = cb[l * H + lane];     // i%32 invariant per thread (strides are mult of 32)
    float lsum = 0.f, lsq = 0.f;
    float* psum = &g_poolsum[l * BB * H];
    float* pmax = &g_poolmax[l * BB * H];
    for (int i = blockIdx.x * blockDim.x + tid; i < NN * H; i += gridDim.x * blockDim.x) {
        int n = i >> 5;
        float hv = g_h[i];
        float nx = bias + g_agg[i] * g_invdeg[n] + g_hr[i];
        g_agg[i] = 0.f;                 // ready for next layer
        int g = batch[n];
        atomicAdd(&psum[g * H + lane], nx);
        atomicMaxFloat(&pmax[g * H + lane], nx);
        float hp = fmaxf(nx, 0.f) + hv;
        g_hnew[i] = hp;
        lsum += hp; lsq += hp * hp;
    }
    atomicAdd(&ssum[lane], lsum);
    atomicAdd(&ssq[lane], lsq);
    __syncthreads();
    if (tid < H) {
        g_bnpartS[blockIdx.x * H + tid] = ssum[tid];
        g_bnpartQ[blockIdx.x * H + tid] = ssq[tid];
    }
}

// ---------------- fused pool-finish + BN-finish ----------------
__global__ void k_post(const float* __restrict__ gamma, const float* __restrict__ beta, int l) {
    int i = blockIdx.x * blockDim.x + threadIdx.x;
    if (i < BB * H) {
        int g = i / H, k = i % H;
        float cnt = g_cnt[g];
        float m  = g_poolsum[l * BB * H + i] / fmaxf(cnt, 1.f);
        float mx = (cnt > 0.f) ? g_poolmax[l * BB * H + i] : 0.f;
        g_feats[g * FEAT + 53 + l * 2 * H + k]     = m;
        g_feats[g * FEAT + 53 + l * 2 * H + H + k] = mx;
    }
    if (i < H) {
        float s = 0.f, q = 0.f;
        for (int b = 0; b < NBU; b++) {
            s += g_bnpartS[b * H + i];
            q += g_bnpartQ[b * H + i];
        }
        float mu  = s / (float)NN;
        float var = q / (float)NN - mu * mu;
        float A = gamma[l * H + i] * rsqrtf(var + 1e-5f);
        g_bnA[l * H + i] = A;
        g_bnB[l * H + i] = beta[l * H + i] - mu * A;
    }
}

// ---------------- final MLP: feats[B,245]@W0 relu @W1 (8 graphs per block, float4 LDS) ----------------
__global__ void k_final(const float* __restrict__ w0, const float* __restrict__ b0,
                        const float* __restrict__ w1, const float* __restrict__ b1,
                        float* __restrict__ out) {
    __shared__ float sf[GPB * FEATP];
    __shared__ float st[GPB * HLD];
    int tid = threadIdx.x;
    int g0 = blockIdx.x * GPB;
    for (int i = tid; i < GPB * FEATP; i += blockDim.x) {
        int gg = i / FEATP, r = i - gg * FEATP;
        sf[i] = (r < FEAT) ? g_feats[(g0 + gg) * FEAT + r] : 0.f;
    }
    __syncthreads();
    {
        float acc[GPB];
        float bb = b0[tid];
#pragma unroll
        for (int gg = 0; gg < GPB; gg++) acc[gg] = bb;
        for (int i = 0; i < 244; i += 4) {
            float wa = w0[(i + 0) * HLD + tid];
            float wb = w0[(i + 1) * HLD + tid];
            float wc = w0[(i + 2) * HLD + tid];
            float wd = w0[(i + 3) * HLD + tid];
#pragma unroll
            for (int gg = 0; gg < GPB; gg++) {
                float4 f = *(const float4*)&sf[gg * FEATP + i];   // broadcast LDS.128
                acc[gg] = fmaf(f.x, wa, acc[gg]);
                acc[gg] = fmaf(f.y, wb, acc[gg]);
                acc[gg] = fmaf(f.z, wc, acc[gg]);
                acc[gg] = fmaf(f.w, wd, acc[gg]);
            }
        }
        float wl = w0[244 * HLD + tid];
#pragma unroll
        for (int gg = 0; gg < GPB; gg++) acc[gg] = fmaf(sf[gg * FEATP + 244], wl, acc[gg]);
#pragma unroll
        for (int gg = 0; gg < GPB; gg++) st[gg * HLD + tid] = fmaxf(acc[gg], 0.f);
    }
    __syncthreads();
    {
        int col = tid & 127;
        int gbase = (tid >> 7) * 4;
        float bb = b1[col];
        float acc[4];
#pragma unroll
        for (int q = 0; q < 4; q++) acc[q] = bb;
        for (int i = 0; i < HLD; i += 4) {
            float wa = w1[(i + 0) * 2 * LAT + col];
            float wb = w1[(i + 1) * 2 * LAT + col];
            float wc = w1[(i + 2) * 2 * LAT + col];
            float wd = w1[(i + 3) * 2 * LAT + col];
#pragma unroll
            for (int q = 0; q < 4; q++) {
                float4 s4 = *(const float4*)&st[(gbase + q) * HLD + i];  // broadcast LDS.128
                acc[q] = fmaf(s4.x, wa, acc[q]);
                acc[q] = fmaf(s4.y, wb, acc[q]);
                acc[q] = fmaf(s4.z, wc, acc[q]);
                acc[q] = fmaf(s4.w, wd, acc[q]);
            }
        }
#pragma unroll
        for (int q = 0; q < 4; q++) {
            int g = g0 + gbase + q;
            if (col < LAT) out[g * LAT + col] = acc[q];
            else           out[BB * LAT + g * LAT + (col - LAT)] = acc[q];
        }
    }
}

// ---------------- launch ----------------
extern "C" void kernel_launch(void* const* d_in, const int* in_sizes, int n_in,
                              void* d_out, int out_size) {
    const float* x      = (const float*)d_in[0];
    const int*   ei     = (const int*)  d_in[1];
    const float* et     = (const float*)d_in[2];
    const int*   batch  = (const int*)  d_in[3];
    const float* mlp0_w = (const float*)d_in[4];
    const float* mlp0_b = (const float*)d_in[5];
    const float* mlp1_w = (const float*)d_in[6];
    const float* mlp1_b = (const float*)d_in[7];
    const float* enw    = (const float*)d_in[8];
    const float* enb    = (const float*)d_in[9];
    const float* rw     = (const float*)d_in[10];
    const float* cb     = (const float*)d_in[11];
    const float* gamma  = (const float*)d_in[12];
    const float* beta   = (const float*)d_in[13];
    const float* f0w    = (const float*)d_in[14];
    const float* f0b    = (const float*)d_in[15];
    const float* f1w    = (const float*)d_in[16];
    const float* f1b    = (const float*)d_in[17];
    float* out = (float*)d_out;

    k_zero<<<(NN * H / 4 + 255) / 256, 256>>>();
    k_stats<<<(NN * ATT + 255) / 256, 256>>>(ei, et, x, batch);
    k_init_mlp<<<(NN + 255) / 256, 256>>>(x, mlp0_w, mlp0_b, mlp1_w, mlp1_b);

    for (int l = 0; l < LL; l++) {
        k_precompute<<<(NN / 4 + 7) / 8, 256>>>(enw, enb, rw, l);   // 8 warps * 4 nodes per block
        k_edge<<<(EE * 32 + 255) / 256, 256>>>(ei, et);
        k_update<<<NBU, 256>>>(cb, batch, l);
        k_post<<<(BB * H + 255) / 256, 256>>>(gamma, beta, l);
    }

    k_final<<<BB / GPB, 256>>>(f0w, f0b, f1w, f1b, out);
}

// round 6
// speedup vs baseline: 1.2345x; 1.0897x over previous
#include <cuda_runtime.h>
#include <math.h>

#define NN   50000
#define EE   200000
#define BB   2048
#define ATT  16
#define ETT  4
#define H    32
#define LL   3
#define LAT  64
#define HLD  256
#define FEAT 245
#define FEATP 248
#define MAXN 50.0f
#define GPB  8
#define NBU  592   // grid-stride blocks for k_update

// ---------------- scratch (device globals; no allocation allowed) ----------------
__device__ float g_h[NN * H];            // current (normalized) node features
__device__ float g_hnew[NN * H];         // pre-BN features (relu(nx)+h)
__device__ float g_P[NN * 5 * H];        // per-node h@W_t (t=0..3) and h@Bmat (t=4)
__device__ float g_hr[NN * H];           // per-node h@root_w
__device__ float g_agg[NN * H];
__device__ float g_deg[NN];
__device__ float g_invdeg[NN];
__device__ float g_cnt[BB];
__device__ float g_feats[BB * FEAT];
__device__ float g_poolsum[LL * BB * H];
__device__ float g_poolmax[LL * BB * H];
__device__ float g_bnpartS[NBU * H];
__device__ float g_bnpartQ[NBU * H];
__device__ float g_bnA[LL * H];
__device__ float g_bnB[LL * H];

// float atomic max via monotone int/uint mapping
__device__ __forceinline__ void atomicMaxFloat(float* addr, float v) {
    if (v >= 0.f) atomicMax((int*)addr, __float_as_int(v));
    else          atomicMin((unsigned int*)addr, __float_as_uint(v));
}

// vector reduction: one instruction, 16B per lane
__device__ __forceinline__ void redAddF4(float* addr, float4 v) {
    asm volatile("red.global.add.v4.f32 [%0], {%1, %2, %3, %4};"
                 :: "l"(addr), "f"(v.x), "f"(v.y), "f"(v.z), "f"(v.w) : "memory");
}

// ---------------- one-time zero (float4) ----------------
__global__ void k_zero() {
    int i = blockIdx.x * blockDim.x + threadIdx.x;
    const float4 z4 = make_float4(0.f, 0.f, 0.f, 0.f);
    const float4 ninf4 = make_float4(-INFINITY, -INFINITY, -INFINITY, -INFINITY);
    if (i < NN * H / 4)      ((float4*)g_agg)[i] = z4;
    if (i < BB * FEAT / 4)   ((float4*)g_feats)[i] = z4;
    if (i < NN / 4)          ((float4*)g_deg)[i] = z4;
    if (i < BB / 4)          ((float4*)g_cnt)[i] = z4;
    if (i < LL * BB * H / 4) { ((float4*)g_poolsum)[i] = z4; ((float4*)g_poolmax)[i] = ninf4; }
}

// ---------------- fused edge stats + x pools ----------------
__global__ void k_stats(const int* __restrict__ ei, const float* __restrict__ et,
                        const float* __restrict__ x, const int* __restrict__ batch) {
    int i = blockIdx.x * blockDim.x + threadIdx.x;
    if (i < NN * ATT) {
        int n = i / ATT, c = i % ATT;
        int g = batch[n];
        float v = x[i];
        atomicAdd(&g_feats[g * FEAT + 21 + c], v);
        atomicMaxFloat(&g_feats[g * FEAT + 37 + c], v);   // x >= 0, zero-init safe
        if (c == 0) atomicAdd(&g_cnt[g], 1.f);
    }
    if (i < EE) {
        int s = ei[i];
        int t = ei[EE + i];
        atomicAdd(&g_deg[t], 1.f);
        int g = batch[s];
        const float inv = 1.f / MAXN;
#pragma unroll
        for (int j = 0; j < ETT; j++)
            atomicAdd(&g_feats[g * FEAT + 1 + j], et[i * ETT + j] * inv);
    }
}

// ---------------- initial node MLP (thread per node; broadcast-LDS.128 weights)
//                  + fused invdeg / x-feature finish ----------------
__global__ void k_init_mlp(const float* __restrict__ x,
                           const float* __restrict__ w0, const float* __restrict__ b0,
                           const float* __restrict__ w1, const float* __restrict__ b1) {
    __shared__ float sw0[ATT * H], sw1[H * H], sb0[H], sb1[H];
    int tid = threadIdx.x;
    for (int i = tid; i < ATT * H; i += blockDim.x) sw0[i] = w0[i];
    for (int i = tid; i < H * H;  i += blockDim.x) sw1[i] = w1[i];
    if (tid < H) { sb0[tid] = b0[tid]; sb1[tid] = b1[tid]; }
    __syncthreads();

    int gid = blockIdx.x * blockDim.x + tid;
    // fused: invdeg + x-feature finish (depend only on k_stats)
    if (gid < NN) g_invdeg[gid] = 1.f / fmaxf(g_deg[gid], 1.f);
    if (gid < BB * ATT) {
        int g = gid / ATT, c = gid % ATT;
        float cnt = g_cnt[g];
        float sum = g_feats[g * FEAT + 21 + c];
        g_feats[g * FEAT + 5 + c]  = sum / MAXN;
        g_feats[g * FEAT + 21 + c] = sum / fmaxf(cnt, 1.f);
        if (cnt <= 0.f) g_feats[g * FEAT + 37 + c] = 0.f;
        if (c == 0) g_feats[g * FEAT] = cnt / MAXN;
    }

    int n = gid;
    if (n >= NN) return;
    float xr[ATT];
#pragma unroll
    for (int q = 0; q < ATT / 4; q++) {
        float4 v = *(const float4*)&x[n * ATT + q * 4];
        xr[q * 4 + 0] = v.x; xr[q * 4 + 1] = v.y; xr[q * 4 + 2] = v.z; xr[q * 4 + 3] = v.w;
    }
    float t[H];
#pragma unroll
    for (int o = 0; o < H / 4; o++) {
        float4 bv = *(const float4*)&sb0[o * 4];
        t[o * 4 + 0] = bv.x; t[o * 4 + 1] = bv.y; t[o * 4 + 2] = bv.z; t[o * 4 + 3] = bv.w;
    }
#pragma unroll
    for (int a = 0; a < ATT; a++) {
        float xa = xr[a];
#pragma unroll
        for (int o = 0; o < H / 4; o++) {
            float4 w = *(const float4*)&sw0[a * H + o * 4];   // broadcast LDS.128
            t[o * 4 + 0] = fmaf(xa, w.x, t[o * 4 + 0]);
            t[o * 4 + 1] = fmaf(xa, w.y, t[o * 4 + 1]);
            t[o * 4 + 2] = fmaf(xa, w.z, t[o * 4 + 2]);
            t[o * 4 + 3] = fmaf(xa, w.w, t[o * 4 + 3]);
        }
    }
    float hv[H];
#pragma unroll
    for (int o = 0; o < H / 4; o++) {
        float4 bv = *(const float4*)&sb1[o * 4];
        hv[o * 4 + 0] = bv.x; hv[o * 4 + 1] = bv.y; hv[o * 4 + 2] = bv.z; hv[o * 4 + 3] = bv.w;
    }
#pragma unroll
    for (int k = 0; k < H; k++) {
        float tk = fmaxf(t[k], 0.f);
#pragma unroll
        for (int o = 0; o < H / 4; o++) {
            float4 w = *(const float4*)&sw1[k * H + o * 4];   // broadcast LDS.128
            hv[o * 4 + 0] = fmaf(tk, w.x, hv[o * 4 + 0]);
            hv[o * 4 + 1] = fmaf(tk, w.y, hv[o * 4 + 1]);
            hv[o * 4 + 2] = fmaf(tk, w.z, hv[o * 4 + 2]);
            hv[o * 4 + 3] = fmaf(tk, w.w, hv[o * 4 + 3]);
        }
    }
#pragma unroll
    for (int o = 0; o < H / 4; o++)
        *(float4*)&g_h[n * H + o * 4] = make_float4(hv[o*4], hv[o*4+1], hv[o*4+2], hv[o*4+3]);
}

// ---------------- precompute GEMM: P[n,t,:], hr[n,:]; applies prev-layer BN affine
//                  4 nodes per warp ----------------
__global__ void k_precompute(const float* __restrict__ enw, const float* __restrict__ enb,
                             const float* __restrict__ rw, int l) {
    __shared__ float sW[6 * H * H];   // 24 KB: 4 edge-type mats + bias mat + root mat
    int tid = threadIdx.x;
    for (int i = tid; i < 5 * H * H; i += blockDim.x) {
        int t = i >> 10, rest = i & 1023;
        sW[i] = (t < 4) ? enw[(l * ETT + t) * H * H + rest] : enb[l * H * H + rest];
    }
    for (int i = tid; i < H * H; i += blockDim.x)
        sW[5 * H * H + i] = rw[l * H * H + i];
    __syncthreads();

    int warp = (blockIdx.x * blockDim.x + tid) >> 5;
    int lane = tid & 31;
    int nb = warp * 4;
    if (nb >= NN) return;

    float bnA = 0.f, bnB = 0.f;
    if (l > 0) { bnA = g_bnA[(l - 1) * H + lane]; bnB = g_bnB[(l - 1) * H + lane]; }

    float hv[4];
#pragma unroll
    for (int j = 0; j < 4; j++) {
        int n = nb + j;
        if (n < NN) {
            float v;
            if (l == 0) v = g_h[n * H + lane];
            else { v = fmaf(g_hnew[n * H + lane], bnA, bnB); g_h[n * H + lane] = v; }
            hv[j] = v;
        } else hv[j] = 0.f;
    }

    float a0[4] = {0,0,0,0}, a1[4] = {0,0,0,0}, a2[4] = {0,0,0,0};
    float a3[4] = {0,0,0,0}, a4[4] = {0,0,0,0}, a5[4] = {0,0,0,0};
#pragma unroll
    for (int hh = 0; hh < H; hh++) {
        float w0 = sW[0 * 1024 + hh * H + lane];
        float w1 = sW[1 * 1024 + hh * H + lane];
        float w2 = sW[2 * 1024 + hh * H + lane];
        float w3 = sW[3 * 1024 + hh * H + lane];
        float w4 = sW[4 * 1024 + hh * H + lane];
        float w5 = sW[5 * 1024 + hh * H + lane];
#pragma unroll
        for (int j = 0; j < 4; j++) {
            float hb = __shfl_sync(0xffffffffu, hv[j], hh);
            a0[j] = fmaf(hb, w0, a0[j]);
            a1[j] = fmaf(hb, w1, a1[j]);
            a2[j] = fmaf(hb, w2, a2[j]);
            a3[j] = fmaf(hb, w3, a3[j]);
            a4[j] = fmaf(hb, w4, a4[j]);
            a5[j] = fmaf(hb, w5, a5[j]);
        }
    }
#pragma unroll
    for (int j = 0; j < 4; j++) {
        int n = nb + j;
        if (n >= NN) break;
        float* Pr = &g_P[n * 5 * H];
        Pr[0 * H + lane] = a0[j];
        Pr[1 * H + lane] = a1[j];
        Pr[2 * H + lane] = a2[j];
        Pr[3 * H + lane] = a3[j];
        Pr[4 * H + lane] = a4[j];
        g_hr[n * H + lane] = a5[j];
    }
}

// ---------------- edge pass (octet per edge, float4 lanes, vector RED):
//                  msg = Σ_t et·P[src,t,:] + P[src,4,:] → scatter-add ----------------
__global__ void k_edge(const int* __restrict__ ei, const float* __restrict__ et) {
    int gid = blockIdx.x * blockDim.x + threadIdx.x;
    int e = gid >> 3;          // 8 lanes per edge
    int q = gid & 7;           // channel quad q*4 .. q*4+3
    if (e >= EE) return;
    int s = ei[e];
    int t = ei[EE + e];
    float4 ev = *(const float4*)&et[e * ETT];
    const float4* __restrict__ Pr = (const float4*)&g_P[s * 5 * H];
    float4 p0 = Pr[0 * 8 + q];
    float4 p1 = Pr[1 * 8 + q];
    float4 p2 = Pr[2 * 8 + q];
    float4 p3 = Pr[3 * 8 + q];
    float4 p4 = Pr[4 * 8 + q];
    float4 acc;
    acc.x = fmaf(ev.x, p0.x, fmaf(ev.y, p1.x, fmaf(ev.z, p2.x, fmaf(ev.w, p3.x, p4.x))));
    acc.y = fmaf(ev.x, p0.y, fmaf(ev.y, p1.y, fmaf(ev.z, p2.y, fmaf(ev.w, p3.y, p4.y))));
    acc.z = fmaf(ev.x, p0.z, fmaf(ev.y, p1.z, fmaf(ev.z, p2.z, fmaf(ev.w, p3.z, p4.z))));
    acc.w = fmaf(ev.x, p0.w, fmaf(ev.y, p1.w, fmaf(ev.z, p2.w, fmaf(ev.w, p3.w, p4.w))));
    redAddF4(&g_agg[t * H + q * 4], acc);
}

// ---------------- node update (grid-stride streaming, lane=channel): nx = hr + agg*invdeg + b;
//                  pools (warp-coalesced single-line atomics); hnew = relu(nx)+h; BN partials; re-zero agg ----------------
__global__ void k_update(const float* __restrict__ cb, const int* __restrict__ batch, int l) {
    __shared__ float ssum[H], ssq[H];
    int tid = threadIdx.x;
    int lane = tid & 31;
    if (tid < H) { ssum[tid] = 0.f; ssq[tid] = 0.f; }
    __syncthreads();
    float bias = cb[l * H + lane];     // i%32 invariant per thread (strides are mult of 32)
    float lsum = 0.f, lsq = 0.f;
    float* psum = &g_poolsum[l * BB * H];
    float* pmax = &g_poolmax[l * BB * H];
    for (int i = blockIdx.x * blockDim.x + tid; i < NN * H; i += gridDim.x * blockDim.x) {
        int n = i >> 5;
        float hv = g_h[i];
        float nx = bias + g_agg[i] * g_invdeg[n] + g_hr[i];
        g_agg[i] = 0.f;                 // ready for next layer
        int g = batch[n];
        atomicAdd(&psum[g * H + lane], nx);
        atomicMaxFloat(&pmax[g * H + lane], nx);
        float hp = fmaxf(nx, 0.f) + hv;
        g_hnew[i] = hp;
        lsum += hp; lsq += hp * hp;
    }
    atomicAdd(&ssum[lane], lsum);
    atomicAdd(&ssq[lane], lsq);
    __syncthreads();
    if (tid < H) {
        g_bnpartS[blockIdx.x * H + tid] = ssum[tid];
        g_bnpartQ[blockIdx.x * H + tid] = ssq[tid];
    }
}

// ---------------- fused pool-finish + BN-finish ----------------
__global__ void k_post(const float* __restrict__ gamma, const float* __restrict__ beta, int l) {
    int i = blockIdx.x * blockDim.x + threadIdx.x;
    if (i < BB * H) {
        int g = i / H, k = i % H;
        float cnt = g_cnt[g];
        float m  = g_poolsum[l * BB * H + i] / fmaxf(cnt, 1.f);
        float mx = (cnt > 0.f) ? g_poolmax[l * BB * H + i] : 0.f;
        g_feats[g * FEAT + 53 + l * 2 * H + k]     = m;
        g_feats[g * FEAT + 53 + l * 2 * H + H + k] = mx;
    }
    if (i < H) {
        float s = 0.f, q = 0.f;
        for (int b = 0; b < NBU; b++) {
            s += g_bnpartS[b * H + i];
            q += g_bnpartQ[b * H + i];
        }
        float mu  = s / (float)NN;
        float var = q / (float)NN - mu * mu;
        float A = gamma[l * H + i] * rsqrtf(var + 1e-5f);
        g_bnA[l * H + i] = A;
        g_bnB[l * H + i] = beta[l * H + i] - mu * A;
    }
}

// ---------------- final MLP: feats[B,245]@W0 relu @W1 (8 graphs per block, float4 LDS) ----------------
__global__ void k_final(const float* __restrict__ w0, const float* __restrict__ b0,
                        const float* __restrict__ w1, const float* __restrict__ b1,
                        float* __restrict__ out) {
    __shared__ float sf[GPB * FEATP];
    __shared__ float st[GPB * HLD];
    int tid = threadIdx.x;
    int g0 = blockIdx.x * GPB;
    for (int i = tid; i < GPB * FEATP; i += blockDim.x) {
        int gg = i / FEATP, r = i - gg * FEATP;
        sf[i] = (r < FEAT) ? g_feats[(g0 + gg) * FEAT + r] : 0.f;
    }
    __syncthreads();
    {
        float acc[GPB];
        float bb = b0[tid];
#pragma unroll
        for (int gg = 0; gg < GPB; gg++) acc[gg] = bb;
        for (int i = 0; i < 244; i += 4) {
            float wa = w0[(i + 0) * HLD + tid];
            float wb = w0[(i + 1) * HLD + tid];
            float wc = w0[(i + 2) * HLD + tid];
            float wd = w0[(i + 3) * HLD + tid];
#pragma unroll
            for (int gg = 0; gg < GPB; gg++) {
                float4 f = *(const float4*)&sf[gg * FEATP + i];   // broadcast LDS.128
                acc[gg] = fmaf(f.x, wa, acc[gg]);
                acc[gg] = fmaf(f.y, wb, acc[gg]);
                acc[gg] = fmaf(f.z, wc, acc[gg]);
                acc[gg] = fmaf(f.w, wd, acc[gg]);
            }
        }
        float wl = w0[244 * HLD + tid];
#pragma unroll
        for (int gg = 0; gg < GPB; gg++) acc[gg] = fmaf(sf[gg * FEATP + 244], wl, acc[gg]);
#pragma unroll
        for (int gg = 0; gg < GPB; gg++) st[gg * HLD + tid] = fmaxf(acc[gg], 0.f);
    }
    __syncthreads();
    {
        int col = tid & 127;
        int gbase = (tid >> 7) * 4;
        float bb = b1[col];
        float acc[4];
#pragma unroll
        for (int q = 0; q < 4; q++) acc[q] = bb;
        for (int i = 0; i < HLD; i += 4) {
            float wa = w1[(i + 0) * 2 * LAT + col];
            float wb = w1[(i + 1) * 2 * LAT + col];
            float wc = w1[(i + 2) * 2 * LAT + col];
            float wd = w1[(i + 3) * 2 * LAT + col];
#pragma unroll
            for (int q = 0; q < 4; q++) {
                float4 s4 = *(const float4*)&st[(gbase + q) * HLD + i];  // broadcast LDS.128
                acc[q] = fmaf(s4.x, wa, acc[q]);
                acc[q] = fmaf(s4.y, wb, acc[q]);
                acc[q] = fmaf(s4.z, wc, acc[q]);
                acc[q] = fmaf(s4.w, wd, acc[q]);
            }
        }
#pragma unroll
        for (int q = 0; q < 4; q++) {
            int g = g0 + gbase + q;
            if (col < LAT) out[g * LAT + col] = acc[q];
            else           out[BB * LAT + g * LAT + (col - LAT)] = acc[q];
        }
    }
}

// ---------------- launch ----------------
extern "C" void kernel_launch(void* const* d_in, const int* in_sizes, int n_in,
                              void* d_out, int out_size) {
    const float* x      = (const float*)d_in[0];
    const int*   ei     = (const int*)  d_in[1];
    const float* et     = (const float*)d_in[2];
    const int*   batch  = (const int*)  d_in[3];
    const float* mlp0_w = (const float*)d_in[4];
    const float* mlp0_b = (const float*)d_in[5];
    const float* mlp1_w = (const float*)d_in[6];
    const float* mlp1_b = (const float*)d_in[7];
    const float* enw    = (const float*)d_in[8];
    const float* enb    = (const float*)d_in[9];
    const float* rw     = (const float*)d_in[10];
    const float* cb     = (const float*)d_in[11];
    const float* gamma  = (const float*)d_in[12];
    const float* beta   = (const float*)d_in[13];
    const float* f0w    = (const float*)d_in[14];
    const float* f0b    = (const float*)d_in[15];
    const float* f1w    = (const float*)d_in[16];
    const float* f1b    = (const float*)d_in[17];
    float* out = (float*)d_out;

    k_zero<<<(NN * H / 4 + 255) / 256, 256>>>();
    k_stats<<<(NN * ATT + 255) / 256, 256>>>(ei, et, x, batch);
    k_init_mlp<<<(NN + 255) / 256, 256>>>(x, mlp0_w, mlp0_b, mlp1_w, mlp1_b);

    for (int l = 0; l < LL; l++) {
        k_precompute<<<(NN / 4 + 7) / 8, 256>>>(enw, enb, rw, l);   // 8 warps * 4 nodes per block
        k_edge<<<(EE * 8 + 255) / 256, 256>>>(ei, et);
        k_update<<<NBU, 256>>>(cb, batch, l);
        k_post<<<(BB * H + 255) / 256, 256>>>(gamma, beta, l);
    }

    k_final<<<BB / GPB, 256>>>(f0w, f0b, f1w, f1b, out);
}

// round 7
// speedup vs baseline: 1.3135x; 1.0640x over previous
#include <cuda_runtime.h>
#include <cuda_fp16.h>
#include <math.h>

#define NN   50000
#define EE   200000
#define BB   2048
#define ATT  16
#define ETT  4
#define H    32
#define LL   3
#define LAT  64
#define HLD  256
#define FEAT 245
#define FEATP 248
#define MAXN 50.0f
#define GPB  8
#define NBU  592   // grid-stride blocks for k_update

// ---------------- scratch (device globals; no allocation allowed) ----------------
__device__ float  g_h[NN * H];           // current (normalized) node features
__device__ float  g_hnew[NN * H];        // pre-BN features (relu(nx)+h)
__device__ __half g_Ph[NN * 5 * H];      // fp16: per-node h@W_t (t=0..3) and h@Bmat (t=4)
__device__ float  g_hr[NN * H];          // per-node h@root_w (fp32)
__device__ float  g_agg[NN * H];
__device__ float  g_deg[NN];
__device__ float  g_invdeg[NN];
__device__ float  g_cnt[BB];
__device__ float  g_feats[BB * FEAT];
__device__ float  g_poolsum[LL * BB * H];
__device__ float  g_poolmax[LL * BB * H];
__device__ float  g_bnpartS[NBU * H];
__device__ float  g_bnpartQ[NBU * H];
__device__ float  g_bnA[LL * H];
__device__ float  g_bnB[LL * H];

// float atomic max via monotone int/uint mapping
__device__ __forceinline__ void atomicMaxFloat(float* addr, float v) {
    if (v >= 0.f) atomicMax((int*)addr, __float_as_int(v));
    else          atomicMin((unsigned int*)addr, __float_as_uint(v));
}

// vector reduction: one instruction, 16B per lane
__device__ __forceinline__ void redAddF4(float* addr, float4 v) {
    asm volatile("red.global.add.v4.f32 [%0], {%1, %2, %3, %4};"
                 :: "l"(addr), "f"(v.x), "f"(v.y), "f"(v.z), "f"(v.w) : "memory");
}

// load 4 consecutive halves (8B) and widen to float4
__device__ __forceinline__ float4 ldP4h(const __half* p) {
    uint2 u = *(const uint2*)p;
    __half2 a = *reinterpret_cast<__half2*>(&u.x);
    __half2 b = *reinterpret_cast<__half2*>(&u.y);
    float2 fa = __half22float2(a), fb = __half22float2(b);
    return make_float4(fa.x, fa.y, fb.x, fb.y);
}

// ---------------- one-time zero (float4) ----------------
__global__ void k_zero() {
    int i = blockIdx.x * blockDim.x + threadIdx.x;
    const float4 z4 = make_float4(0.f, 0.f, 0.f, 0.f);
    const float4 ninf4 = make_float4(-INFINITY, -INFINITY, -INFINITY, -INFINITY);
    if (i < NN * H / 4)      ((float4*)g_agg)[i] = z4;
    if (i < BB * FEAT / 4)   ((float4*)g_feats)[i] = z4;
    if (i < NN / 4)          ((float4*)g_deg)[i] = z4;
    if (i < BB / 4)          ((float4*)g_cnt)[i] = z4;
    if (i < LL * BB * H / 4) { ((float4*)g_poolsum)[i] = z4; ((float4*)g_poolmax)[i] = ninf4; }
}

// ---------------- fused edge stats + x pools ----------------
__global__ void k_stats(const int* __restrict__ ei, const float* __restrict__ et,
                        const float* __restrict__ x, const int* __restrict__ batch) {
    int i = blockIdx.x * blockDim.x + threadIdx.x;
    if (i < NN * ATT) {
        int n = i / ATT, c = i % ATT;
        int g = batch[n];
        float v = x[i];
        atomicAdd(&g_feats[g * FEAT + 21 + c], v);
        atomicMaxFloat(&g_feats[g * FEAT + 37 + c], v);   // x >= 0, zero-init safe
        if (c == 0) atomicAdd(&g_cnt[g], 1.f);
    }
    if (i < EE) {
        int s = ei[i];
        int t = ei[EE + i];
        atomicAdd(&g_deg[t], 1.f);
        int g = batch[s];
        const float inv = 1.f / MAXN;
#pragma unroll
        for (int j = 0; j < ETT; j++)
            atomicAdd(&g_feats[g * FEAT + 1 + j], et[i * ETT + j] * inv);
    }
}

// ---------------- initial node MLP (thread per node; broadcast-LDS.128 weights)
//                  + fused invdeg / x-feature finish ----------------
__global__ void k_init_mlp(const float* __restrict__ x,
                           const float* __restrict__ w0, const float* __restrict__ b0,
                           const float* __restrict__ w1, const float* __restrict__ b1) {
    __shared__ float sw0[ATT * H], sw1[H * H], sb0[H], sb1[H];
    int tid = threadIdx.x;
    for (int i = tid; i < ATT * H; i += blockDim.x) sw0[i] = w0[i];
    for (int i = tid; i < H * H;  i += blockDim.x) sw1[i] = w1[i];
    if (tid < H) { sb0[tid] = b0[tid]; sb1[tid] = b1[tid]; }
    __syncthreads();

    int gid = blockIdx.x * blockDim.x + tid;
    // fused: invdeg + x-feature finish (depend only on k_stats)
    if (gid < NN) g_invdeg[gid] = 1.f / fmaxf(g_deg[gid], 1.f);
    if (gid < BB * ATT) {
        int g = gid / ATT, c = gid % ATT;
        float cnt = g_cnt[g];
        float sum = g_feats[g * FEAT + 21 + c];
        g_feats[g * FEAT + 5 + c]  = sum / MAXN;
        g_feats[g * FEAT + 21 + c] = sum / fmaxf(cnt, 1.f);
        if (cnt <= 0.f) g_feats[g * FEAT + 37 + c] = 0.f;
        if (c == 0) g_feats[g * FEAT] = cnt / MAXN;
    }

    int n = gid;
    if (n >= NN) return;
    float xr[ATT];
#pragma unroll
    for (int q = 0; q < ATT / 4; q++) {
        float4 v = *(const float4*)&x[n * ATT + q * 4];
        xr[q * 4 + 0] = v.x; xr[q * 4 + 1] = v.y; xr[q * 4 + 2] = v.z; xr[q * 4 + 3] = v.w;
    }
    float t[H];
#pragma unroll
    for (int o = 0; o < H / 4; o++) {
        float4 bv = *(const float4*)&sb0[o * 4];
        t[o * 4 + 0] = bv.x; t[o * 4 + 1] = bv.y; t[o * 4 + 2] = bv.z; t[o * 4 + 3] = bv.w;
    }
#pragma unroll
    for (int a = 0; a < ATT; a++) {
        float xa = xr[a];
#pragma unroll
        for (int o = 0; o < H / 4; o++) {
            float4 w = *(const float4*)&sw0[a * H + o * 4];   // broadcast LDS.128
            t[o * 4 + 0] = fmaf(xa, w.x, t[o * 4 + 0]);
            t[o * 4 + 1] = fmaf(xa, w.y, t[o * 4 + 1]);
            t[o * 4 + 2] = fmaf(xa, w.z, t[o * 4 + 2]);
            t[o * 4 + 3] = fmaf(xa, w.w, t[o * 4 + 3]);
        }
    }
    float hv[H];
#pragma unroll
    for (int o = 0; o < H / 4; o++) {
        float4 bv = *(const float4*)&sb1[o * 4];
        hv[o * 4 + 0] = bv.x; hv[o * 4 + 1] = bv.y; hv[o * 4 + 2] = bv.z; hv[o * 4 + 3] = bv.w;
    }
#pragma unroll
    for (int k = 0; k < H; k++) {
        float tk = fmaxf(t[k], 0.f);
#pragma unroll
        for (int o = 0; o < H / 4; o++) {
            float4 w = *(const float4*)&sw1[k * H + o * 4];   // broadcast LDS.128
            hv[o * 4 + 0] = fmaf(tk, w.x, hv[o * 4 + 0]);
            hv[o * 4 + 1] = fmaf(tk, w.y, hv[o * 4 + 1]);
            hv[o * 4 + 2] = fmaf(tk, w.z, hv[o * 4 + 2]);
            hv[o * 4 + 3] = fmaf(tk, w.w, hv[o * 4 + 3]);
        }
    }
#pragma unroll
    for (int o = 0; o < H / 4; o++)
        *(float4*)&g_h[n * H + o * 4] = make_float4(hv[o*4], hv[o*4+1], hv[o*4+2], hv[o*4+3]);
}

// ---------------- precompute GEMM: Ph[n,t,:] (fp16), hr[n,:] (fp32); applies prev-layer BN affine
//                  4 nodes per warp ----------------
__global__ void k_precompute(const float* __restrict__ enw, const float* __restrict__ enb,
                             const float* __restrict__ rw, int l) {
    __shared__ float sW[6 * H * H];   // 24 KB: 4 edge-type mats + bias mat + root mat
    int tid = threadIdx.x;
    for (int i = tid; i < 5 * H * H; i += blockDim.x) {
        int t = i >> 10, rest = i & 1023;
        sW[i] = (t < 4) ? enw[(l * ETT + t) * H * H + rest] : enb[l * H * H + rest];
    }
    for (int i = tid; i < H * H; i += blockDim.x)
        sW[5 * H * H + i] = rw[l * H * H + i];
    __syncthreads();

    int warp = (blockIdx.x * blockDim.x + tid) >> 5;
    int lane = tid & 31;
    int nb = warp * 4;
    if (nb >= NN) return;

    float bnA = 0.f, bnB = 0.f;
    if (l > 0) { bnA = g_bnA[(l - 1) * H + lane]; bnB = g_bnB[(l - 1) * H + lane]; }

    float hv[4];
#pragma unroll
    for (int j = 0; j < 4; j++) {
        int n = nb + j;
        if (n < NN) {
            float v;
            if (l == 0) v = g_h[n * H + lane];
            else { v = fmaf(g_hnew[n * H + lane], bnA, bnB); g_h[n * H + lane] = v; }
            hv[j] = v;
        } else hv[j] = 0.f;
    }

    float a0[4] = {0,0,0,0}, a1[4] = {0,0,0,0}, a2[4] = {0,0,0,0};
    float a3[4] = {0,0,0,0}, a4[4] = {0,0,0,0}, a5[4] = {0,0,0,0};
#pragma unroll
    for (int hh = 0; hh < H; hh++) {
        float w0 = sW[0 * 1024 + hh * H + lane];
        float w1 = sW[1 * 1024 + hh * H + lane];
        float w2 = sW[2 * 1024 + hh * H + lane];
        float w3 = sW[3 * 1024 + hh * H + lane];
        float w4 = sW[4 * 1024 + hh * H + lane];
        float w5 = sW[5 * 1024 + hh * H + lane];
#pragma unroll
        for (int j = 0; j < 4; j++) {
            float hb = __shfl_sync(0xffffffffu, hv[j], hh);
            a0[j] = fmaf(hb, w0, a0[j]);
            a1[j] = fmaf(hb, w1, a1[j]);
            a2[j] = fmaf(hb, w2, a2[j]);
            a3[j] = fmaf(hb, w3, a3[j]);
            a4[j] = fmaf(hb, w4, a4[j]);
            a5[j] = fmaf(hb, w5, a5[j]);
        }
    }
#pragma unroll
    for (int j = 0; j < 4; j++) {
        int n = nb + j;
        if (n >= NN) break;
        __half* Pr = &g_Ph[n * 5 * H];
        Pr[0 * H + lane] = __float2half(a0[j]);
        Pr[1 * H + lane] = __float2half(a1[j]);
        Pr[2 * H + lane] = __float2half(a2[j]);
        Pr[3 * H + lane] = __float2half(a3[j]);
        Pr[4 * H + lane] = __float2half(a4[j]);
        g_hr[n * H + lane] = a5[j];
    }
}

// ---------------- edge pass (octet per edge, fp16 P gather, fp32 math, vector RED):
//                  msg = Σ_t et·P[src,t,:] + P[src,4,:] → scatter-add ----------------
__global__ void k_edge(const int* __restrict__ ei, const float* __restrict__ et) {
    int gid = blockIdx.x * blockDim.x + threadIdx.x;
    int e = gid >> 3;          // 8 lanes per edge
    int q = gid & 7;           // channel quad q*4 .. q*4+3
    if (e >= EE) return;
    int s = ei[e];
    int t = ei[EE + e];
    float4 ev = *(const float4*)&et[e * ETT];
    const __half* __restrict__ Pr = &g_Ph[s * 5 * H];
    float4 p0 = ldP4h(&Pr[0 * H + q * 4]);
    float4 p1 = ldP4h(&Pr[1 * H + q * 4]);
    float4 p2 = ldP4h(&Pr[2 * H + q * 4]);
    float4 p3 = ldP4h(&Pr[3 * H + q * 4]);
    float4 p4 = ldP4h(&Pr[4 * H + q * 4]);
    float4 acc;
    acc.x = fmaf(ev.x, p0.x, fmaf(ev.y, p1.x, fmaf(ev.z, p2.x, fmaf(ev.w, p3.x, p4.x))));
    acc.y = fmaf(ev.x, p0.y, fmaf(ev.y, p1.y, fmaf(ev.z, p2.y, fmaf(ev.w, p3.y, p4.y))));
    acc.z = fmaf(ev.x, p0.z, fmaf(ev.y, p1.z, fmaf(ev.z, p2.z, fmaf(ev.w, p3.z, p4.z))));
    acc.w = fmaf(ev.x, p0.w, fmaf(ev.y, p1.w, fmaf(ev.z, p2.w, fmaf(ev.w, p3.w, p4.w))));
    redAddF4(&g_agg[t * H + q * 4], acc);
}

// ---------------- node update (grid-stride streaming, lane=channel): nx = hr + agg*invdeg + b;
//                  pools (warp-coalesced single-line atomics); hnew = relu(nx)+h; BN partials; re-zero agg ----------------
__global__ void k_update(const float* __restrict__ cb, const int* __restrict__ batch, int l) {
    __shared__ float ssum[H], ssq[H];
    int tid = threadIdx.x;
    int lane = tid & 31;
    if (tid < H) { ssum[tid] = 0.f; ssq[tid] = 0.f; }
    __syncthreads();
    float bias = cb[l * H + lane];     // i%32 invariant per thread (strides are mult of 32)
    float lsum = 0.f, lsq = 0.f;
    float* psum = &g_poolsum[l * BB * H];
    float* pmax = &g_poolmax[l * BB * H];
    for (int i = blockIdx.x * blockDim.x + tid; i < NN * H; i += gridDim.x * blockDim.x) {
        int n = i >> 5;
        float hv = g_h[i];
        float nx = bias + g_agg[i] * g_invdeg[n] + g_hr[i];
        g_agg[i] = 0.f;                 // ready for next layer
        int g = batch[n];
        atomicAdd(&psum[g * H + lane], nx);
        atomicMaxFloat(&pmax[g * H + lane], nx);
        float hp = fmaxf(nx, 0.f) + hv;
        g_hnew[i] = hp;
        lsum += hp; lsq += hp * hp;
    }
    atomicAdd(&ssum[lane], lsum);
    atomicAdd(&ssq[lane], lsq);
    __syncthreads();
    if (tid < H) {
        g_bnpartS[blockIdx.x * H + tid] = ssum[tid];
        g_bnpartQ[blockIdx.x * H + tid] = ssq[tid];
    }
}

// ---------------- fused pool-finish + BN-finish ----------------
__global__ void k_post(const float* __restrict__ gamma, const float* __restrict__ beta, int l) {
    int i = blockIdx.x * blockDim.x + threadIdx.x;
    if (i < BB * H) {
        int g = i / H, k = i % H;
        float cnt = g_cnt[g];
        float m  = g_poolsum[l * BB * H + i] / fmaxf(cnt, 1.f);
        float mx = (cnt > 0.f) ? g_poolmax[l * BB * H + i] : 0.f;
        g_feats[g * FEAT + 53 + l * 2 * H + k]     = m;
        g_feats[g * FEAT + 53 + l * 2 * H + H + k] = mx;
    }
    if (i < H) {
        float s = 0.f, q = 0.f;
        for (int b = 0; b < NBU; b++) {
            s += g_bnpartS[b * H + i];
            q += g_bnpartQ[b * H + i];
        }
        float mu  = s / (float)NN;
        float var = q / (float)NN - mu * mu;
        float A = gamma[l * H + i] * rsqrtf(var + 1e-5f);
        g_bnA[l * H + i] = A;
        g_bnB[l * H + i] = beta[l * H + i] - mu * A;
    }
}

// ---------------- final MLP: feats[B,245]@W0 relu @W1 (8 graphs per block, float4 LDS) ----------------
__global__ void k_final(const float* __restrict__ w0, const float* __restrict__ b0,
                        const float* __restrict__ w1, const float* __restrict__ b1,
                        float* __restrict__ out) {
    __shared__ float sf[GPB * FEATP];
    __shared__ float st[GPB * HLD];
    int tid = threadIdx.x;
    int g0 = blockIdx.x * GPB;
    for (int i = tid; i < GPB * FEATP; i += blockDim.x) {
        int gg = i / FEATP, r = i - gg * FEATP;
        sf[i] = (r < FEAT) ? g_feats[(g0 + gg) * FEAT + r] : 0.f;
    }
    __syncthreads();
    {
        float acc[GPB];
        float bb = b0[tid];
#pragma unroll
        for (int gg = 0; gg < GPB; gg++) acc[gg] = bb;
        for (int i = 0; i < 244; i += 4) {
            float wa = w0[(i + 0) * HLD + tid];
            float wb = w0[(i + 1) * HLD + tid];
            float wc = w0[(i + 2) * HLD + tid];
            float wd = w0[(i + 3) * HLD + tid];
#pragma unroll
            for (int gg = 0; gg < GPB; gg++) {
                float4 f = *(const float4*)&sf[gg * FEATP + i];   // broadcast LDS.128
                acc[gg] = fmaf(f.x, wa, acc[gg]);
                acc[gg] = fmaf(f.y, wb, acc[gg]);
                acc[gg] = fmaf(f.z, wc, acc[gg]);
                acc[gg] = fmaf(f.w, wd, acc[gg]);
            }
        }
        float wl = w0[244 * HLD + tid];
#pragma unroll
        for (int gg = 0; gg < GPB; gg++) acc[gg] = fmaf(sf[gg * FEATP + 244], wl, acc[gg]);
#pragma unroll
        for (int gg = 0; gg < GPB; gg++) st[gg * HLD + tid] = fmaxf(acc[gg], 0.f);
    }
    __syncthreads();
    {
        int col = tid & 127;
        int gbase = (tid >> 7) * 4;
        float bb = b1[col];
        float acc[4];
#pragma unroll
        for (int q = 0; q < 4; q++) acc[q] = bb;
        for (int i = 0; i < HLD; i += 4) {
            float wa = w1[(i + 0) * 2 * LAT + col];
            float wb = w1[(i + 1) * 2 * LAT + col];
            float wc = w1[(i + 2) * 2 * LAT + col];
            float wd = w1[(i + 3) * 2 * LAT + col];
#pragma unroll
            for (int q = 0; q < 4; q++) {
                float4 s4 = *(const float4*)&st[(gbase + q) * HLD + i];  // broadcast LDS.128
                acc[q] = fmaf(s4.x, wa, acc[q]);
                acc[q] = fmaf(s4.y, wb, acc[q]);
                acc[q] = fmaf(s4.z, wc, acc[q]);
                acc[q] = fmaf(s4.w, wd, acc[q]);
            }
        }
#pragma unroll
        for (int q = 0; q < 4; q++) {
            int g = g0 + gbase + q;
            if (col < LAT) out[g * LAT + col] = acc[q];
            else           out[BB * LAT + g * LAT + (col - LAT)] = acc[q];
        }
    }
}

// ---------------- launch ----------------
extern "C" void kernel_launch(void* const* d_in, const int* in_sizes, int n_in,
                              void* d_out, int out_size) {
    const float* x      = (const float*)d_in[0];
    const int*   ei     = (const int*)  d_in[1];
    const float* et     = (const float*)d_in[2];
    const int*   batch  = (const int*)  d_in[3];
    const float* mlp0_w = (const float*)d_in[4];
    const float* mlp0_b = (const float*)d_in[5];
    const float* mlp1_w = (const float*)d_in[6];
    const float* mlp1_b = (const float*)d_in[7];
    const float* enw    = (const float*)d_in[8];
    const float* enb    = (const float*)d_in[9];
    const float* rw     = (const float*)d_in[10];
    const float* cb     = (const float*)d_in[11];
    const float* gamma  = (const float*)d_in[12];
    const float* beta   = (const float*)d_in[13];
    const float* f0w    = (const float*)d_in[14];
    const float* f0b    = (const float*)d_in[15];
    const float* f1w    = (const float*)d_in[16];
    const float* f1b    = (const float*)d_in[17];
    float* out = (float*)d_out;

    k_zero<<<(NN * H / 4 + 255) / 256, 256>>>();
    k_stats<<<(NN * ATT + 255) / 256, 256>>>(ei, et, x, batch);
    k_init_mlp<<<(NN + 255) / 256, 256>>>(x, mlp0_w, mlp0_b, mlp1_w, mlp1_b);

    for (int l = 0; l < LL; l++) {
        k_precompute<<<(NN / 4 + 7) / 8, 256>>>(enw, enb, rw, l);   // 8 warps * 4 nodes per block
        k_edge<<<(EE * 8 + 255) / 256, 256>>>(ei, et);
        k_update<<<NBU, 256>>>(cb, batch, l);
        k_post<<<(BB * H + 255) / 256, 256>>>(gamma, beta, l);
    }

    k_final<<<BB / GPB, 256>>>(f0w, f0b, f1w, f1b, out);
}